// round 2
// baseline (speedup 1.0000x reference)
#include <cuda_runtime.h>
#include <cuda_bf16.h>
#include <cuda_fp16.h>
#include <cstdint>

// ============================================================================
// Problem constants
// ============================================================================
static constexpr int B_ROWS = 131072;
static constexpr int KC     = 512;
static constexpr int TM     = 128;
static constexpr int NTILES = B_ROWS / TM;   // 1024

// ============================================================================
// SMEM layout (bytes)
// ============================================================================
static constexpr int OFF_ZSQ = 0;        // 128 f32
static constexpr int OFF_CSQ = 512;      // 512 f32 -> 2048 B
static constexpr int OFF_W   = 2560;     // 128 * 9 f32 = 4608 B (per-row, per-chunk weights)
static constexpr int OFF_RED = 7168;     // 8 f32 warp loss partials
static constexpr int OFF_AHI = 8192;     // z-hi  128 x 128B = 16 KB
static constexpr int OFF_ALO = 24576;    // z-lo  16 KB
static constexpr int OFF_BHI = 40960;    // c-hi  512 x 128B = 64 KB
static constexpr int OFF_BLO = 106496;   // c-lo  64 KB
static constexpr int SMEM_BYTES = 172032;
// e-staging for chunk n aliases B rows [64n,64n+64): rows 0-63 of the tile go
// into BHI + n*8192, rows 64-127 into BLO + n*8192 (dead after chunk-n MMA).

__device__ float g_loss_partial[NTILES];

#define SWZ(o) ((o) ^ (((o) >> 3) & 0x70))

// ============================================================================
// Helpers
// ============================================================================
__device__ __forceinline__ uint32_t smem_u32(const void* p) {
    uint32_t a;
    asm("{ .reg .u64 t; cvta.to.shared.u64 t, %1; cvt.u32.u64 %0, t; }" : "=r"(a) : "l"(p));
    return a;
}

__device__ __forceinline__ void ldsm4(uint32_t r[4], uint32_t addr) {
    asm volatile("ldmatrix.sync.aligned.m8n8.x4.shared.b16 {%0,%1,%2,%3}, [%4];"
                 : "=r"(r[0]), "=r"(r[1]), "=r"(r[2]), "=r"(r[3]) : "r"(addr));
}

__device__ __forceinline__ void mma16816(float* d, const uint32_t* a, uint32_t b0, uint32_t b1) {
    asm volatile("mma.sync.aligned.m16n8k16.row.col.f32.bf16.bf16.f32 "
                 "{%0,%1,%2,%3}, {%4,%5,%6,%7}, {%8,%9}, {%0,%1,%2,%3};"
                 : "+f"(d[0]), "+f"(d[1]), "+f"(d[2]), "+f"(d[3])
                 : "r"(a[0]), "r"(a[1]), "r"(a[2]), "r"(a[3]), "r"(b0), "r"(b1));
}

// split (x,y) into bf16 hi pair + bf16 residual pair (packed b32 each)
__device__ __forceinline__ void split2(float x, float y, uint32_t& hi, uint32_t& lo) {
    __nv_bfloat16 hx = __float2bfloat16(x), hy = __float2bfloat16(y);
    float rx = x - __bfloat162float(hx);
    float ry = y - __bfloat162float(hy);
    __nv_bfloat162 h(hx, hy);
    __nv_bfloat162 l(__float2bfloat16(rx), __float2bfloat16(ry));
    hi = *reinterpret_cast<uint32_t*>(&h);
    lo = *reinterpret_cast<uint32_t*>(&l);
}

// ============================================================================
// Main kernel: one CTA per 128-row tile, 256 threads (8 warps x m16 tile)
// ============================================================================
__global__ void __launch_bounds__(256, 1)
soft_kmeans_kernel(const float* __restrict__ z, const float* __restrict__ cc,
                   float* __restrict__ q_out) {
    extern __shared__ char smem[];
    const uint32_t sb = smem_u32(smem);
    const int tid  = threadIdx.x;
    const int lane = tid & 31;
    const int wid  = tid >> 5;
    const int tile = blockIdx.x;

    float* zsq_s = reinterpret_cast<float*>(smem + OFF_ZSQ);
    float* csq_s = reinterpret_cast<float*>(smem + OFF_CSQ);
    float* w_s   = reinterpret_cast<float*>(smem + OFF_W);
    float* red_s = reinterpret_cast<float*>(smem + OFF_RED);

    // ---- Phase 0a: z tile, coalesced float4; split hi/lo (pre-scaled x2) ---
    {
        const float4* zt = reinterpret_cast<const float4*>(z) + (size_t)tile * (TM * 64 / 4);
        #pragma unroll
        for (int it = 0; it < 8; it++) {
            const int idx = it * 256 + tid;
            const int row = idx >> 4, c4 = idx & 15;
            const float4 v = zt[idx];
            float sq = v.x * v.x + v.y * v.y + v.z * v.z + v.w * v.w;
            sq += __shfl_xor_sync(~0u, sq, 1);
            sq += __shfl_xor_sync(~0u, sq, 2);
            sq += __shfl_xor_sync(~0u, sq, 4);
            sq += __shfl_xor_sync(~0u, sq, 8);
            if ((lane & 15) == 0) zsq_s[row] = sq;
            uint2 hi, lo;
            split2(2.f * v.x, 2.f * v.y, hi.x, lo.x);
            split2(2.f * v.z, 2.f * v.w, hi.y, lo.y);
            const uint32_t so = SWZ((uint32_t)(row * 128 + c4 * 8));
            *reinterpret_cast<uint2*>(smem + OFF_AHI + so) = hi;
            *reinterpret_cast<uint2*>(smem + OFF_ALO + so) = lo;
        }
    }
    // ---- Phase 0b: all 512 centers, same pattern (no x2) -------------------
    {
        const float4* ct = reinterpret_cast<const float4*>(cc);
        #pragma unroll 4
        for (int it = 0; it < 32; it++) {
            const int idx = it * 256 + tid;
            const int row = idx >> 4, c4 = idx & 15;
            const float4 v = ct[idx];
            float sq = v.x * v.x + v.y * v.y + v.z * v.z + v.w * v.w;
            sq += __shfl_xor_sync(~0u, sq, 1);
            sq += __shfl_xor_sync(~0u, sq, 2);
            sq += __shfl_xor_sync(~0u, sq, 4);
            sq += __shfl_xor_sync(~0u, sq, 8);
            if ((lane & 15) == 0) csq_s[row] = sq;
            uint2 hi, lo;
            split2(v.x, v.y, hi.x, lo.x);
            split2(v.z, v.w, hi.y, lo.y);
            const uint32_t so = SWZ((uint32_t)(row * 128 + c4 * 8));
            *reinterpret_cast<uint2*>(smem + OFF_BHI + so) = hi;
            *reinterpret_cast<uint2*>(smem + OFF_BLO + so) = lo;
        }
    }
    __syncthreads();

    // ---- ldmatrix lane decodes ---------------------------------------------
    const int l8 = lane & 7;
    // A x4 groups: g0 rows 0-7 kLo, g1 rows 8-15 kLo, g2 rows 0-7 kHi, g3 rows 8-15 kHi
    const uint32_t aRow  = wid * 16 + ((lane >> 3) & 1) * 8 + l8;
    const uint32_t aOff0 = aRow * 128 + ((lane >> 4) & 1) * 16;
    // B x4 groups: g0 n0-7 kLo, g1 n0-7 kHi, g2 n8-15 kLo, g3 n8-15 kHi
    const uint32_t bRowL = ((lane >> 4) & 1) * 8 + l8;
    const uint32_t bK16  = ((lane >> 3) & 1) * 16;

    // fragment rows owned by this thread
    const int r0 = wid * 16 + (lane >> 2);
    const int r1 = r0 + 8;
    const float zq0 = zsq_s[r0], zq1 = zsq_s[r1];

    // e-staging bases (chunk term ch*8192 added per chunk); intra-offset
    // decomposition: (nt*16 + (lane&3)*4) ^ ((row&7)*16) == ((nt^(row&7))*16) + (lane&3)*4
    const uint32_t eb0 = (r0 < 64 ? OFF_BHI + (uint32_t)r0 * 128
                                  : OFF_BLO + (uint32_t)(r0 - 64) * 128) + (lane & 3) * 4;
    const uint32_t eb1 = (r1 < 64 ? OFF_BHI + (uint32_t)r1 * 128
                                  : OFF_BLO + (uint32_t)(r1 - 64) * 128) + (lane & 3) * 4;

    float m0 = -1e30f, s0 = 0.f, t0 = 0.f;
    float m1 = -1e30f, s1 = 0.f, t1 = 0.f;

    // ---- Pass 1: 8 N-chunks of 64 clusters ---------------------------------
    for (int ch = 0; ch < 8; ch++) {
        float acc[32];
        #pragma unroll
        for (int i = 0; i < 32; i++) acc[i] = 0.f;

        // 3 split terms: (Ahi,Bhi) + (Ahi,Blo) + (Alo,Bhi)
        #pragma unroll
        for (int term = 0; term < 3; term++) {
            const uint32_t aB = sb + (term == 2 ? OFF_ALO : OFF_AHI);
            const uint32_t bB = sb + (term == 1 ? OFF_BLO : OFF_BHI);
            #pragma unroll
            for (int ks = 0; ks < 4; ks++) {
                uint32_t a[4];
                ldsm4(a, aB + SWZ(aOff0 + ks * 32));
                uint32_t b[4][4];
                #pragma unroll
                for (int p = 0; p < 4; p++) {
                    const uint32_t bo = (uint32_t)(ch * 64 + p * 16 + bRowL) * 128 + bK16 + ks * 32;
                    ldsm4(b[p], bB + SWZ(bo));
                }
                #pragma unroll
                for (int p = 0; p < 4; p++) {
                    mma16816(acc + p * 8,     a, b[p][0], b[p][1]);
                    mma16816(acc + p * 8 + 4, a, b[p][2], b[p][3]);
                }
            }
        }

        // y = cross2 - zsq - csq = -dist; overwrite acc with y, chunk max
        float cm0 = -1e30f, cm1 = -1e30f;
        #pragma unroll
        for (int nt = 0; nt < 8; nt++) {
            const float2 cs = *reinterpret_cast<const float2*>(
                csq_s + ch * 64 + nt * 8 + (lane & 3) * 2);
            float* A = acc + nt * 4;
            A[0] = A[0] - zq0 - cs.x;
            A[1] = A[1] - zq0 - cs.y;
            A[2] = A[2] - zq1 - cs.x;
            A[3] = A[3] - zq1 - cs.y;
            cm0 = fmaxf(cm0, fmaxf(A[0], A[1]));
            cm1 = fmaxf(cm1, fmaxf(A[2], A[3]));
        }
        cm0 = fmaxf(cm0, __shfl_xor_sync(~0u, cm0, 1));
        cm0 = fmaxf(cm0, __shfl_xor_sync(~0u, cm0, 2));
        cm1 = fmaxf(cm1, __shfl_xor_sync(~0u, cm1, 1));
        cm1 = fmaxf(cm1, __shfl_xor_sync(~0u, cm1, 2));
        const float nm0 = fmaxf(m0, cm0), nm1 = fmaxf(m1, cm1);
        const float f0 = __expf(m0 - nm0), f1 = __expf(m1 - nm1);
        s0 *= f0; t0 *= f0; m0 = nm0;
        s1 *= f1; t1 *= f1; m1 = nm1;

        __syncthreads();  // all warps finished reading B[ch] -> safe to alias

        const uint32_t ebase0 = eb0 + (uint32_t)ch * 8192;
        const uint32_t ebase1 = eb1 + (uint32_t)ch * 8192;
        #pragma unroll
        for (int nt = 0; nt < 8; nt++) {
            float* A = acc + nt * 4;
            const float e00 = __expf(A[0] - m0), e01 = __expf(A[1] - m0);
            const float e10 = __expf(A[2] - m1), e11 = __expf(A[3] - m1);
            s0 += e00 + e01;  t0 -= e00 * A[0] + e01 * A[1];   // dist = -y
            s1 += e10 + e11;  t1 -= e10 * A[2] + e11 * A[3];
            const __half2 h0 = __floats2half2_rn(e00, e01);
            const __half2 h1 = __floats2half2_rn(e10, e11);
            *reinterpret_cast<__half2*>(smem + ebase0 + (uint32_t)((nt ^ (r0 & 7)) * 16)) = h0;
            *reinterpret_cast<__half2*>(smem + ebase1 + (uint32_t)((nt ^ (r1 & 7)) * 16)) = h1;
        }
        if ((lane & 3) == 0) {
            w_s[r0 * 9 + ch] = m0;
            w_s[r1 * 9 + ch] = m1;
        }
    }

    // ---- finalize rows: quad reductions, weights, loss ---------------------
    s0 += __shfl_xor_sync(~0u, s0, 1);  s0 += __shfl_xor_sync(~0u, s0, 2);
    t0 += __shfl_xor_sync(~0u, t0, 1);  t0 += __shfl_xor_sync(~0u, t0, 2);
    s1 += __shfl_xor_sync(~0u, s1, 1);  s1 += __shfl_xor_sync(~0u, s1, 2);
    t1 += __shfl_xor_sync(~0u, t1, 1);  t1 += __shfl_xor_sync(~0u, t1, 2);
    const float inv0 = 1.f / s0, inv1 = 1.f / s1;
    if ((lane & 3) == 0) {
        #pragma unroll
        for (int c = 0; c < 8; c++) {
            w_s[r0 * 9 + c] = __expf(w_s[r0 * 9 + c] - m0) * inv0;
            w_s[r1 * 9 + c] = __expf(w_s[r1 * 9 + c] - m1) * inv1;
        }
    }
    float lr = ((lane & 3) == 0) ? (t0 * inv0 + t1 * inv1) : 0.f;
    #pragma unroll
    for (int o = 16; o; o >>= 1) lr += __shfl_xor_sync(~0u, lr, o);
    if (lane == 0) red_s[wid] = lr;
    __syncthreads();
    if (tid == 0) {
        float a = 0.f;
        #pragma unroll
        for (int i = 0; i < 8; i++) a += red_s[i];
        g_loss_partial[tile] = a;
    }

    // ---- Pass 2: coalesced q write (warp = chunk, lane = col pair) ---------
    float* qb = q_out + (size_t)tile * TM * KC + wid * 64 + lane * 2;
    const uint32_t ecol = (uint32_t)lane * 4;
    const uint32_t chOff = (uint32_t)wid * 8192;
    #pragma unroll 4
    for (int row = 0; row < TM; row++) {
        const uint32_t base = (row < 64 ? OFF_BHI + (uint32_t)row * 128
                                        : OFF_BLO + (uint32_t)(row - 64) * 128) + chOff;
        const uint32_t u = *reinterpret_cast<const uint32_t*>(
            smem + base + (ecol ^ (uint32_t)((row & 7) * 16)));
        const float2 f = __half22float2(*reinterpret_cast<const __half2*>(&u));
        const float w = w_s[row * 9 + wid];
        float2 o;
        o.x = f.x * w;
        o.y = f.y * w;
        *reinterpret_cast<float2*>(qb + (size_t)row * KC) = o;
    }
}

// ============================================================================
// Loss reduce: sum 1024 partials in fp64, write mean
// ============================================================================
__global__ void loss_reduce_kernel(float* __restrict__ loss_out) {
    __shared__ double sm[8];
    const int tid = threadIdx.x;
    double a = 0.0;
    for (int i = tid; i < NTILES; i += 256) a += (double)g_loss_partial[i];
    #pragma unroll
    for (int o = 16; o; o >>= 1) a += __shfl_xor_sync(~0u, a, o);
    if ((tid & 31) == 0) sm[tid >> 5] = a;
    __syncthreads();
    if (tid == 0) {
        double t = 0.0;
        #pragma unroll
        for (int i = 0; i < 8; i++) t += sm[i];
        *loss_out = (float)(t / (double)B_ROWS);
    }
}

// ============================================================================
// Launch
// ============================================================================
extern "C" void kernel_launch(void* const* d_in, const int* in_sizes, int n_in,
                              void* d_out, int out_size) {
    const float* z  = (const float*)d_in[0];
    const float* cc = (const float*)d_in[1];
    float* q = (float*)d_out;

    cudaFuncSetAttribute(soft_kmeans_kernel,
                         cudaFuncAttributeMaxDynamicSharedMemorySize, SMEM_BYTES);
    soft_kmeans_kernel<<<NTILES, 256, SMEM_BYTES>>>(z, cc, q);

    const long long q_elems = (long long)B_ROWS * KC;  // 67108864
    if ((long long)out_size > q_elems) {
        loss_reduce_kernel<<<1, 256>>>(q + q_elems);
    }
}

// round 4
// speedup vs baseline: 1.0591x; 1.0591x over previous
#include <cuda_runtime.h>
#include <cuda_bf16.h>
#include <cuda_fp16.h>
#include <cstdint>

// ============================================================================
// Problem constants
// ============================================================================
static constexpr int B_ROWS = 131072;
static constexpr int KC     = 512;
static constexpr int TM     = 128;
static constexpr int NTILES = B_ROWS / TM;   // 1024

// ============================================================================
// SMEM layout (bytes)
// ============================================================================
static constexpr int OFF_ZSQ = 0;        // 128 f32
static constexpr int OFF_CSQ = 512;      // 512 f32 -> 2048 B
static constexpr int OFF_W   = 2560;     // 128 * 9 f32 = 4608 B
static constexpr int OFF_RED = 7168;     // 8 f32 warp loss partials + flag
static constexpr int OFF_AHI = 8192;     // z-hi  128 x 128B = 16 KB
static constexpr int OFF_ALO = 24576;    // z-lo  16 KB
static constexpr int OFF_BHI = 40960;    // c-hi  512 x 128B = 64 KB
static constexpr int OFF_BLO = 106496;   // c-lo  64 KB
static constexpr int SMEM_BYTES = 172032;
// e-staging for chunk n aliases B rows [64n,64n+64): tile rows 0-63 go into
// BHI + n*8192, rows 64-127 into BLO + n*8192 (dead after chunk-n MMA).

__device__ float g_loss_partial[NTILES];
__device__ unsigned int g_done;   // zero-init; reset to 0 by last CTA each run

#define SWZ(o) ((o) ^ (((o) >> 3) & 0x70))

// ============================================================================
// Helpers
// ============================================================================
__device__ __forceinline__ uint32_t smem_u32(const void* p) {
    uint32_t a;
    asm("{ .reg .u64 t; cvta.to.shared.u64 t, %1; cvt.u32.u64 %0, t; }" : "=r"(a) : "l"(p));
    return a;
}

__device__ __forceinline__ void ldsm4(uint32_t r[4], uint32_t addr) {
    asm volatile("ldmatrix.sync.aligned.m8n8.x4.shared.b16 {%0,%1,%2,%3}, [%4];"
                 : "=r"(r[0]), "=r"(r[1]), "=r"(r[2]), "=r"(r[3]) : "r"(addr));
}

__device__ __forceinline__ void mma16816(float* d, const uint32_t* a, uint32_t b0, uint32_t b1) {
    asm volatile("mma.sync.aligned.m16n8k16.row.col.f32.bf16.bf16.f32 "
                 "{%0,%1,%2,%3}, {%4,%5,%6,%7}, {%8,%9}, {%0,%1,%2,%3};"
                 : "+f"(d[0]), "+f"(d[1]), "+f"(d[2]), "+f"(d[3])
                 : "r"(a[0]), "r"(a[1]), "r"(a[2]), "r"(a[3]), "r"(b0), "r"(b1));
}

// split (x,y) into bf16 hi pair + bf16 residual pair (packed b32 each)
__device__ __forceinline__ void split2(float x, float y, uint32_t& hi, uint32_t& lo) {
    __nv_bfloat16 hx = __float2bfloat16(x), hy = __float2bfloat16(y);
    float rx = x - __bfloat162float(hx);
    float ry = y - __bfloat162float(hy);
    __nv_bfloat162 h(hx, hy);
    __nv_bfloat162 l(__float2bfloat16(rx), __float2bfloat16(ry));
    hi = *reinterpret_cast<uint32_t*>(&h);
    lo = *reinterpret_cast<uint32_t*>(&l);
}

// ============================================================================
// Main kernel: one CTA per 128-row tile, 256 threads (8 warps x m16 tile)
// ============================================================================
__global__ void __launch_bounds__(256, 1)
soft_kmeans_kernel(const float* __restrict__ z, const float* __restrict__ cc,
                   float* __restrict__ q_out, float* __restrict__ loss_out) {
    extern __shared__ char smem[];
    const uint32_t sb = smem_u32(smem);
    const int tid  = threadIdx.x;
    const int lane = tid & 31;
    const int wid  = tid >> 5;
    const int tile = blockIdx.x;

    float* zsq_s = reinterpret_cast<float*>(smem + OFF_ZSQ);
    float* csq_s = reinterpret_cast<float*>(smem + OFF_CSQ);
    float* w_s   = reinterpret_cast<float*>(smem + OFF_W);
    float* red_s = reinterpret_cast<float*>(smem + OFF_RED);
    unsigned int* flag_s = reinterpret_cast<unsigned int*>(smem + OFF_RED + 32);

    // ---- Phase 0a: z tile, coalesced float4; split hi/lo (pre-scaled x2) ---
    {
        const float4* zt = reinterpret_cast<const float4*>(z) + (size_t)tile * (TM * 64 / 4);
        #pragma unroll
        for (int it = 0; it < 8; it++) {
            const int idx = it * 256 + tid;
            const int row = idx >> 4, c4 = idx & 15;
            const float4 v = zt[idx];
            float sq = v.x * v.x + v.y * v.y + v.z * v.z + v.w * v.w;
            sq += __shfl_xor_sync(~0u, sq, 1);
            sq += __shfl_xor_sync(~0u, sq, 2);
            sq += __shfl_xor_sync(~0u, sq, 4);
            sq += __shfl_xor_sync(~0u, sq, 8);
            if ((lane & 15) == 0) zsq_s[row] = sq;
            uint2 hi, lo;
            split2(2.f * v.x, 2.f * v.y, hi.x, lo.x);
            split2(2.f * v.z, 2.f * v.w, hi.y, lo.y);
            const uint32_t so = SWZ((uint32_t)(row * 128 + c4 * 8));
            *reinterpret_cast<uint2*>(smem + OFF_AHI + so) = hi;
            *reinterpret_cast<uint2*>(smem + OFF_ALO + so) = lo;
        }
    }
    // ---- Phase 0b: all 512 centers ----------------------------------------
    {
        const float4* ct = reinterpret_cast<const float4*>(cc);
        #pragma unroll 4
        for (int it = 0; it < 32; it++) {
            const int idx = it * 256 + tid;
            const int row = idx >> 4, c4 = idx & 15;
            const float4 v = ct[idx];
            float sq = v.x * v.x + v.y * v.y + v.z * v.z + v.w * v.w;
            sq += __shfl_xor_sync(~0u, sq, 1);
            sq += __shfl_xor_sync(~0u, sq, 2);
            sq += __shfl_xor_sync(~0u, sq, 4);
            sq += __shfl_xor_sync(~0u, sq, 8);
            if ((lane & 15) == 0) csq_s[row] = sq;
            uint2 hi, lo;
            split2(v.x, v.y, hi.x, lo.x);
            split2(v.z, v.w, hi.y, lo.y);
            const uint32_t so = SWZ((uint32_t)(row * 128 + c4 * 8));
            *reinterpret_cast<uint2*>(smem + OFF_BHI + so) = hi;
            *reinterpret_cast<uint2*>(smem + OFF_BLO + so) = lo;
        }
    }
    __syncthreads();

    // ---- ldmatrix lane decodes ---------------------------------------------
    const int l8 = lane & 7;
    const uint32_t aRow  = wid * 16 + ((lane >> 3) & 1) * 8 + l8;
    const uint32_t aOff0 = aRow * 128 + ((lane >> 4) & 1) * 16;
    const uint32_t bRowL = ((lane >> 4) & 1) * 8 + l8;
    const uint32_t bK16  = ((lane >> 3) & 1) * 16;

    // ---- A fragments resident for the whole pass (same for all chunks) -----
    uint32_t Ahi[4][4], Alo[4][4];
    #pragma unroll
    for (int ks = 0; ks < 4; ks++) {
        ldsm4(Ahi[ks], sb + OFF_AHI + SWZ(aOff0 + ks * 32));
        ldsm4(Alo[ks], sb + OFF_ALO + SWZ(aOff0 + ks * 32));
    }

    // fragment rows owned by this thread
    const int r0 = wid * 16 + (lane >> 2);
    const int r1 = r0 + 8;
    const float zq0 = zsq_s[r0], zq1 = zsq_s[r1];

    // e-staging bases: chunk ch's e overwrites exactly B[ch] rows (hi & lo)
    const uint32_t eb0 = (r0 < 64 ? OFF_BHI + (uint32_t)r0 * 128
                                  : OFF_BLO + (uint32_t)(r0 - 64) * 128) + (lane & 3) * 4;
    const uint32_t eb1 = (r1 < 64 ? OFF_BHI + (uint32_t)r1 * 128
                                  : OFF_BLO + (uint32_t)(r1 - 64) * 128) + (lane & 3) * 4;

    float m0 = -1e30f, s0 = 0.f, t0 = 0.f;
    float m1 = -1e30f, s1 = 0.f, t1 = 0.f;

    // ---- Pass 1: 8 N-chunks of 64 clusters ---------------------------------
    for (int ch = 0; ch < 8; ch++) {
        float acc[32];
        #pragma unroll
        for (int i = 0; i < 32; i++) acc[i] = 0.f;

        // fused: per (ks,p) load Bhi/Blo once, feed all 3 split terms
        #pragma unroll
        for (int ks = 0; ks < 4; ks++) {
            #pragma unroll
            for (int p = 0; p < 4; p++) {
                const uint32_t bo = (uint32_t)(ch * 64 + p * 16 + bRowL) * 128 + bK16 + ks * 32;
                uint32_t bh[4], bl[4];
                ldsm4(bh, sb + OFF_BHI + SWZ(bo));
                ldsm4(bl, sb + OFF_BLO + SWZ(bo));
                mma16816(acc + p * 8,     Ahi[ks], bh[0], bh[1]);
                mma16816(acc + p * 8 + 4, Ahi[ks], bh[2], bh[3]);
                mma16816(acc + p * 8,     Ahi[ks], bl[0], bl[1]);
                mma16816(acc + p * 8 + 4, Ahi[ks], bl[2], bl[3]);
                mma16816(acc + p * 8,     Alo[ks], bh[0], bh[1]);
                mma16816(acc + p * 8 + 4, Alo[ks], bh[2], bh[3]);
            }
        }

        // y = cross2 - zsq - csq = -dist; chunk max
        float cm0 = -1e30f, cm1 = -1e30f;
        #pragma unroll
        for (int nt = 0; nt < 8; nt++) {
            const float2 cs = *reinterpret_cast<const float2*>(
                csq_s + ch * 64 + nt * 8 + (lane & 3) * 2);
            float* A = acc + nt * 4;
            A[0] = A[0] - zq0 - cs.x;
            A[1] = A[1] - zq0 - cs.y;
            A[2] = A[2] - zq1 - cs.x;
            A[3] = A[3] - zq1 - cs.y;
            cm0 = fmaxf(cm0, fmaxf(A[0], A[1]));
            cm1 = fmaxf(cm1, fmaxf(A[2], A[3]));
        }
        cm0 = fmaxf(cm0, __shfl_xor_sync(~0u, cm0, 1));
        cm0 = fmaxf(cm0, __shfl_xor_sync(~0u, cm0, 2));
        cm1 = fmaxf(cm1, __shfl_xor_sync(~0u, cm1, 1));
        cm1 = fmaxf(cm1, __shfl_xor_sync(~0u, cm1, 2));
        const float nm0 = fmaxf(m0, cm0), nm1 = fmaxf(m1, cm1);
        const float f0 = __expf(m0 - nm0), f1 = __expf(m1 - nm1);
        s0 *= f0; t0 *= f0; m0 = nm0;
        s1 *= f1; t1 *= f1; m1 = nm1;

        // exps + running sums into regs BEFORE the barrier (overlap MUFU w/ skew)
        uint32_t hp0[8], hp1[8];
        #pragma unroll
        for (int nt = 0; nt < 8; nt++) {
            float* A = acc + nt * 4;
            const float e00 = __expf(A[0] - m0), e01 = __expf(A[1] - m0);
            const float e10 = __expf(A[2] - m1), e11 = __expf(A[3] - m1);
            s0 += e00 + e01;  t0 -= e00 * A[0] + e01 * A[1];   // dist = -y
            s1 += e10 + e11;  t1 -= e10 * A[2] + e11 * A[3];
            const __half2 h0 = __floats2half2_rn(e00, e01);
            const __half2 h1 = __floats2half2_rn(e10, e11);
            hp0[nt] = *reinterpret_cast<const uint32_t*>(&h0);
            hp1[nt] = *reinterpret_cast<const uint32_t*>(&h1);
        }

        __syncthreads();  // all warps finished reading B[ch] -> safe to alias

        const uint32_t ebase0 = eb0 + (uint32_t)ch * 8192;
        const uint32_t ebase1 = eb1 + (uint32_t)ch * 8192;
        #pragma unroll
        for (int nt = 0; nt < 8; nt++) {
            *reinterpret_cast<uint32_t*>(smem + ebase0 + (uint32_t)((nt ^ (r0 & 7)) * 16)) = hp0[nt];
            *reinterpret_cast<uint32_t*>(smem + ebase1 + (uint32_t)((nt ^ (r1 & 7)) * 16)) = hp1[nt];
        }
        if ((lane & 3) == 0) {
            w_s[r0 * 9 + ch] = m0;
            w_s[r1 * 9 + ch] = m1;
        }
    }

    // ---- finalize rows: quad reductions, weights, loss ---------------------
    s0 += __shfl_xor_sync(~0u, s0, 1);  s0 += __shfl_xor_sync(~0u, s0, 2);
    t0 += __shfl_xor_sync(~0u, t0, 1);  t0 += __shfl_xor_sync(~0u, t0, 2);
    s1 += __shfl_xor_sync(~0u, s1, 1);  s1 += __shfl_xor_sync(~0u, s1, 2);
    t1 += __shfl_xor_sync(~0u, t1, 1);  t1 += __shfl_xor_sync(~0u, t1, 2);
    const float inv0 = 1.f / s0, inv1 = 1.f / s1;
    if ((lane & 3) == 0) {
        #pragma unroll
        for (int c = 0; c < 8; c++) {
            w_s[r0 * 9 + c] = __expf(w_s[r0 * 9 + c] - m0) * inv0;
            w_s[r1 * 9 + c] = __expf(w_s[r1 * 9 + c] - m1) * inv1;
        }
    }
    float lr = ((lane & 3) == 0) ? (t0 * inv0 + t1 * inv1) : 0.f;
    #pragma unroll
    for (int o = 16; o; o >>= 1) lr += __shfl_xor_sync(~0u, lr, o);
    if (lane == 0) red_s[wid] = lr;
    __syncthreads();
    if (tid == 0) {
        float a = 0.f;
        #pragma unroll
        for (int i = 0; i < 8; i++) a += red_s[i];
        g_loss_partial[tile] = a;
    }
    __syncthreads();   // w_s finalized before pass 2 reads

    // ---- Pass 2: coalesced q write -----------------------------------------
    // warps 0-3: rows 0-63;  warps 4-7: rows 64-127.  Each warp: 128 cols.
    {
        const int rbase = (wid >> 2) * 64;
        const int cb = (wid & 3) * 128 + lane * 4;
        const int ch = cb >> 6;                       // chunk index 0..7
        const uint32_t chOff = (uint32_t)ch * 8192;
        const uint32_t inrow = (uint32_t)(lane & 15) * 8;  // byte off of col in chunk row
        float* qb = q_out + (size_t)tile * TM * KC + cb;
        #pragma unroll 4
        for (int r = 0; r < 64; r++) {
            const int row = rbase + r;
            const uint32_t base = (rbase ? OFF_BLO + (uint32_t)(row - 64) * 128
                                         : OFF_BHI + (uint32_t)row * 128) + chOff;
            const uint2 u = *reinterpret_cast<const uint2*>(
                smem + base + (inrow ^ (uint32_t)((row & 7) * 16)));
            const float2 f01 = __half22float2(*reinterpret_cast<const __half2*>(&u.x));
            const float2 f23 = __half22float2(*reinterpret_cast<const __half2*>(&u.y));
            const float w = w_s[row * 9 + ch];
            float4 o;
            o.x = f01.x * w; o.y = f01.y * w; o.z = f23.x * w; o.w = f23.y * w;
            *reinterpret_cast<float4*>(qb + (size_t)row * KC) = o;
        }
    }

    // ---- last-CTA loss finalize (deterministic fixed-order sum) ------------
    __threadfence();
    if (tid == 0) {
        const unsigned int old = atomicAdd(&g_done, 1u);
        *flag_s = (old == (unsigned int)(NTILES - 1)) ? 1u : 0u;
    }
    __syncthreads();
    if (*flag_s) {
        double a = 0.0;
        for (int i = tid; i < NTILES; i += 256) a += (double)g_loss_partial[i];
        #pragma unroll
        for (int o = 16; o; o >>= 1) a += __shfl_xor_sync(~0u, a, o);
        double* dred = reinterpret_cast<double*>(smem + OFF_RED + 64);
        if (lane == 0) dred[wid] = a;
        __syncthreads();
        if (tid == 0) {
            double t = 0.0;
            #pragma unroll
            for (int i = 0; i < 8; i++) t += dred[i];
            if (loss_out) *loss_out = (float)(t / (double)B_ROWS);
            g_done = 0;   // reset for next graph replay
        }
    }
}

// ============================================================================
// Launch
// ============================================================================
extern "C" void kernel_launch(void* const* d_in, const int* in_sizes, int n_in,
                              void* d_out, int out_size) {
    const float* z  = (const float*)d_in[0];
    const float* cc = (const float*)d_in[1];
    float* q = (float*)d_out;

    const long long q_elems = (long long)B_ROWS * KC;  // 67108864
    float* loss_out = ((long long)out_size > q_elems) ? (q + q_elems) : nullptr;

    cudaFuncSetAttribute(soft_kmeans_kernel,
                         cudaFuncAttributeMaxDynamicSharedMemorySize, SMEM_BYTES);
    soft_kmeans_kernel<<<NTILES, 256, SMEM_BYTES>>>(z, cc, q, loss_out);
}

// round 5
// speedup vs baseline: 1.1022x; 1.0407x over previous
#include <cuda_runtime.h>
#include <cuda_bf16.h>
#include <cuda_fp16.h>
#include <cstdint>

// ============================================================================
// Problem constants
// ============================================================================
static constexpr int B_ROWS = 131072;
static constexpr int KC     = 512;
static constexpr int TM     = 128;
static constexpr int NTILES = B_ROWS / TM;   // 1024

// ============================================================================
// SMEM layout (bytes)
// ============================================================================
static constexpr int OFF_ZSQ = 0;        // 128 f32
static constexpr int OFF_CSQ = 512;      // 512 f32
static constexpr int OFF_W   = 2560;     // 128 * 9 f32 = 4608 B (chunk-max snapshots -> weights)
static constexpr int OFF_MST = 7168;     // 2 groups * 128 rows * 4 f32 (m,s,t,pad) = 4096 B
static constexpr int OFF_RED = 11264;    // 16 f32 + flag + 16 dbl  (1 KB reserved)
static constexpr int OFF_AHI = 12288;    // z-hi  128 x 128B = 16 KB
static constexpr int OFF_ALO = 28672;    // z-lo  16 KB
static constexpr int OFF_BHI = 45056;    // c-hi  512 x 128B = 64 KB
static constexpr int OFF_BLO = 110592;   // c-lo  64 KB
static constexpr int SMEM_BYTES = 176128;
// e-staging for chunk n aliases B cluster-rows [64n,64n+64): tile rows 0-63 go
// into BHI + n*8192, rows 64-127 into BLO + n*8192 (dead after chunk-n MMA).

__device__ float g_loss_partial[NTILES];
__device__ unsigned int g_done;   // zero-init; reset by last CTA each run

#define SWZ(o) ((o) ^ (((o) >> 3) & 0x70))

// ============================================================================
// Helpers
// ============================================================================
__device__ __forceinline__ uint32_t smem_u32(const void* p) {
    uint32_t a;
    asm("{ .reg .u64 t; cvta.to.shared.u64 t, %1; cvt.u32.u64 %0, t; }" : "=r"(a) : "l"(p));
    return a;
}

__device__ __forceinline__ void ldsm4(uint32_t r[4], uint32_t addr) {
    asm volatile("ldmatrix.sync.aligned.m8n8.x4.shared.b16 {%0,%1,%2,%3}, [%4];"
                 : "=r"(r[0]), "=r"(r[1]), "=r"(r[2]), "=r"(r[3]) : "r"(addr));
}

__device__ __forceinline__ void mma16816(float* d, const uint32_t* a, uint32_t b0, uint32_t b1) {
    asm volatile("mma.sync.aligned.m16n8k16.row.col.f32.bf16.bf16.f32 "
                 "{%0,%1,%2,%3}, {%4,%5,%6,%7}, {%8,%9}, {%0,%1,%2,%3};"
                 : "+f"(d[0]), "+f"(d[1]), "+f"(d[2]), "+f"(d[3])
                 : "r"(a[0]), "r"(a[1]), "r"(a[2]), "r"(a[3]), "r"(b0), "r"(b1));
}

__device__ __forceinline__ void split2(float x, float y, uint32_t& hi, uint32_t& lo) {
    __nv_bfloat16 hx = __float2bfloat16(x), hy = __float2bfloat16(y);
    float rx = x - __bfloat162float(hx);
    float ry = y - __bfloat162float(hy);
    __nv_bfloat162 h(hx, hy);
    __nv_bfloat162 l(__float2bfloat16(rx), __float2bfloat16(ry));
    hi = *reinterpret_cast<uint32_t*>(&h);
    lo = *reinterpret_cast<uint32_t*>(&l);
}

// ============================================================================
// Main kernel: one CTA per 128-row tile, 512 threads
// 16 warps = 8 m16-tiles x 2 N-groups (group = 256 clusters)
// ============================================================================
__global__ void __launch_bounds__(512, 1)
soft_kmeans_kernel(const float* __restrict__ z, const float* __restrict__ cc,
                   float* __restrict__ q_out, float* __restrict__ loss_out) {
    extern __shared__ char smem[];
    const uint32_t sb = smem_u32(smem);
    const int tid  = threadIdx.x;
    const int lane = tid & 31;
    const int wid  = tid >> 5;
    const int tile = blockIdx.x;
    const int mt    = wid & 7;    // m16-tile index (rows mt*16..mt*16+15)
    const int nhalf = wid >> 3;   // 0: cols 0-255 (chunks 0-3), 1: cols 256-511 (chunks 4-7)

    float* zsq_s = reinterpret_cast<float*>(smem + OFF_ZSQ);
    float* csq_s = reinterpret_cast<float*>(smem + OFF_CSQ);
    float* w_s   = reinterpret_cast<float*>(smem + OFF_W);
    float* mst_s = reinterpret_cast<float*>(smem + OFF_MST);
    float* red_s = reinterpret_cast<float*>(smem + OFF_RED);
    unsigned int* flag_s = reinterpret_cast<unsigned int*>(smem + OFF_RED + 64);

    // ---- Phase 0a: z tile, coalesced float4; split hi/lo (pre-scaled x2) ---
    {
        const float4* zt = reinterpret_cast<const float4*>(z) + (size_t)tile * (TM * 64 / 4);
        #pragma unroll
        for (int it = 0; it < 4; it++) {
            const int idx = it * 512 + tid;
            const int row = idx >> 4, c4 = idx & 15;
            const float4 v = zt[idx];
            float sq = v.x * v.x + v.y * v.y + v.z * v.z + v.w * v.w;
            sq += __shfl_xor_sync(~0u, sq, 1);
            sq += __shfl_xor_sync(~0u, sq, 2);
            sq += __shfl_xor_sync(~0u, sq, 4);
            sq += __shfl_xor_sync(~0u, sq, 8);
            if ((lane & 15) == 0) zsq_s[row] = sq;
            uint2 hi, lo;
            split2(2.f * v.x, 2.f * v.y, hi.x, lo.x);
            split2(2.f * v.z, 2.f * v.w, hi.y, lo.y);
            const uint32_t so = SWZ((uint32_t)(row * 128 + c4 * 8));
            *reinterpret_cast<uint2*>(smem + OFF_AHI + so) = hi;
            *reinterpret_cast<uint2*>(smem + OFF_ALO + so) = lo;
        }
    }
    // ---- Phase 0b: all 512 centers ----------------------------------------
    {
        const float4* ct = reinterpret_cast<const float4*>(cc);
        #pragma unroll 4
        for (int it = 0; it < 16; it++) {
            const int idx = it * 512 + tid;
            const int row = idx >> 4, c4 = idx & 15;
            const float4 v = ct[idx];
            float sq = v.x * v.x + v.y * v.y + v.z * v.z + v.w * v.w;
            sq += __shfl_xor_sync(~0u, sq, 1);
            sq += __shfl_xor_sync(~0u, sq, 2);
            sq += __shfl_xor_sync(~0u, sq, 4);
            sq += __shfl_xor_sync(~0u, sq, 8);
            if ((lane & 15) == 0) csq_s[row] = sq;
            uint2 hi, lo;
            split2(v.x, v.y, hi.x, lo.x);
            split2(v.z, v.w, hi.y, lo.y);
            const uint32_t so = SWZ((uint32_t)(row * 128 + c4 * 8));
            *reinterpret_cast<uint2*>(smem + OFF_BHI + so) = hi;
            *reinterpret_cast<uint2*>(smem + OFF_BLO + so) = lo;
        }
    }
    __syncthreads();

    // ---- ldmatrix lane decodes ---------------------------------------------
    const int l8 = lane & 7;
    const uint32_t aRow  = mt * 16 + ((lane >> 3) & 1) * 8 + l8;
    const uint32_t aOff0 = aRow * 128 + ((lane >> 4) & 1) * 16;
    const uint32_t bRowL = ((lane >> 4) & 1) * 8 + l8;
    const uint32_t bK16  = ((lane >> 3) & 1) * 16;

    // fragment rows owned by this thread
    const int r0 = mt * 16 + (lane >> 2);
    const int r1 = r0 + 8;
    const float zq0 = zsq_s[r0], zq1 = zsq_s[r1];

    const uint32_t eb0 = (r0 < 64 ? OFF_BHI + (uint32_t)r0 * 128
                                  : OFF_BLO + (uint32_t)(r0 - 64) * 128) + (lane & 3) * 4;
    const uint32_t eb1 = (r1 < 64 ? OFF_BHI + (uint32_t)r1 * 128
                                  : OFF_BLO + (uint32_t)(r1 - 64) * 128) + (lane & 3) * 4;

    float m0 = -1e30f, s0 = 0.f, t0 = 0.f;
    float m1 = -1e30f, s1 = 0.f, t1 = 0.f;

    // ---- Pass 1: 4 iterations; groups A/B process chunks cc and cc+4 -------
    for (int ccit = 0; ccit < 4; ccit++) {
        const int ch = ccit + nhalf * 4;

        // A fragments (reloaded per iter to cap register pressure)
        uint32_t Ahi[4][4], Alo[4][4];
        #pragma unroll
        for (int ks = 0; ks < 4; ks++) {
            ldsm4(Ahi[ks], sb + OFF_AHI + SWZ(aOff0 + ks * 32));
            ldsm4(Alo[ks], sb + OFF_ALO + SWZ(aOff0 + ks * 32));
        }

        float acc[32];
        #pragma unroll
        for (int i = 0; i < 32; i++) acc[i] = 0.f;

        #pragma unroll
        for (int ks = 0; ks < 4; ks++) {
            #pragma unroll
            for (int p = 0; p < 4; p++) {
                const uint32_t bo = (uint32_t)(ch * 64 + p * 16 + bRowL) * 128 + bK16 + ks * 32;
                uint32_t bh[4], bl[4];
                ldsm4(bh, sb + OFF_BHI + SWZ(bo));
                ldsm4(bl, sb + OFF_BLO + SWZ(bo));
                mma16816(acc + p * 8,     Ahi[ks], bh[0], bh[1]);
                mma16816(acc + p * 8 + 4, Ahi[ks], bh[2], bh[3]);
                mma16816(acc + p * 8,     Ahi[ks], bl[0], bl[1]);
                mma16816(acc + p * 8 + 4, Ahi[ks], bl[2], bl[3]);
                mma16816(acc + p * 8,     Alo[ks], bh[0], bh[1]);
                mma16816(acc + p * 8 + 4, Alo[ks], bh[2], bh[3]);
            }
        }

        // y = cross2 - zsq - csq = -dist; chunk max
        float cm0 = -1e30f, cm1 = -1e30f;
        #pragma unroll
        for (int nt = 0; nt < 8; nt++) {
            const float2 cs = *reinterpret_cast<const float2*>(
                csq_s + ch * 64 + nt * 8 + (lane & 3) * 2);
            float* A = acc + nt * 4;
            A[0] = A[0] - zq0 - cs.x;
            A[1] = A[1] - zq0 - cs.y;
            A[2] = A[2] - zq1 - cs.x;
            A[3] = A[3] - zq1 - cs.y;
            cm0 = fmaxf(cm0, fmaxf(A[0], A[1]));
            cm1 = fmaxf(cm1, fmaxf(A[2], A[3]));
        }
        cm0 = fmaxf(cm0, __shfl_xor_sync(~0u, cm0, 1));
        cm0 = fmaxf(cm0, __shfl_xor_sync(~0u, cm0, 2));
        cm1 = fmaxf(cm1, __shfl_xor_sync(~0u, cm1, 1));
        cm1 = fmaxf(cm1, __shfl_xor_sync(~0u, cm1, 2));
        const float nm0 = fmaxf(m0, cm0), nm1 = fmaxf(m1, cm1);
        const float f0 = __expf(m0 - nm0), f1 = __expf(m1 - nm1);
        s0 *= f0; t0 *= f0; m0 = nm0;
        s1 *= f1; t1 *= f1; m1 = nm1;

        // exps into regs before the aliasing barrier
        uint32_t hp0[8], hp1[8];
        #pragma unroll
        for (int nt = 0; nt < 8; nt++) {
            float* A = acc + nt * 4;
            const float e00 = __expf(A[0] - m0), e01 = __expf(A[1] - m0);
            const float e10 = __expf(A[2] - m1), e11 = __expf(A[3] - m1);
            s0 += e00 + e01;  t0 -= e00 * A[0] + e01 * A[1];   // dist = -y
            s1 += e10 + e11;  t1 -= e10 * A[2] + e11 * A[3];
            const __half2 h0 = __floats2half2_rn(e00, e01);
            const __half2 h1 = __floats2half2_rn(e10, e11);
            hp0[nt] = *reinterpret_cast<const uint32_t*>(&h0);
            hp1[nt] = *reinterpret_cast<const uint32_t*>(&h1);
        }

        __syncthreads();  // all warps done reading B[cc] and B[cc+4] -> alias

        const uint32_t ebase0 = eb0 + (uint32_t)ch * 8192;
        const uint32_t ebase1 = eb1 + (uint32_t)ch * 8192;
        #pragma unroll
        for (int nt = 0; nt < 8; nt++) {
            *reinterpret_cast<uint32_t*>(smem + ebase0 + (uint32_t)((nt ^ (r0 & 7)) * 16)) = hp0[nt];
            *reinterpret_cast<uint32_t*>(smem + ebase1 + (uint32_t)((nt ^ (r1 & 7)) * 16)) = hp1[nt];
        }
        if ((lane & 3) == 0) {
            w_s[r0 * 9 + ch] = m0;   // group-local running-max snapshot
            w_s[r1 * 9 + ch] = m1;
        }
    }

    // ---- group-local row reductions ----------------------------------------
    s0 += __shfl_xor_sync(~0u, s0, 1);  s0 += __shfl_xor_sync(~0u, s0, 2);
    t0 += __shfl_xor_sync(~0u, t0, 1);  t0 += __shfl_xor_sync(~0u, t0, 2);
    s1 += __shfl_xor_sync(~0u, s1, 1);  s1 += __shfl_xor_sync(~0u, s1, 2);
    t1 += __shfl_xor_sync(~0u, t1, 1);  t1 += __shfl_xor_sync(~0u, t1, 2);
    if ((lane & 3) == 0) {
        float* p0 = mst_s + (nhalf * 128 + r0) * 4;
        float* p1 = mst_s + (nhalf * 128 + r1) * 4;
        p0[0] = m0; p0[1] = s0; p0[2] = t0;
        p1[0] = m1; p1[1] = s1; p1[2] = t1;
    }
    __syncthreads();

    // ---- merge halves (thread = row), rescale weights, per-row loss --------
    float lossr = 0.f;
    if (tid < TM) {
        const float* pa = mst_s + tid * 4;
        const float* pb = mst_s + (128 + tid) * 4;
        const float mA = pa[0], sA = pa[1], tA = pa[2];
        const float mB = pb[0], sB = pb[1], tB = pb[2];
        const float m = fmaxf(mA, mB);
        const float fa = __expf(mA - m), fb = __expf(mB - m);
        const float sF = sA * fa + sB * fb;
        const float tF = tA * fa + tB * fb;
        const float inv = 1.f / sF;
        lossr = tF * inv;
        #pragma unroll
        for (int c = 0; c < 8; c++)
            w_s[tid * 9 + c] = __expf(w_s[tid * 9 + c] - m) * inv;
    }
    // loss reduce over rows (warps 0-3 only hold nonzero)
    #pragma unroll
    for (int o = 16; o; o >>= 1) lossr += __shfl_xor_sync(~0u, lossr, o);
    if (wid < 4 && lane == 0) red_s[wid] = lossr;
    __syncthreads();   // w_s + red_s ready
    if (tid == 0)
        g_loss_partial[tile] = red_s[0] + red_s[1] + red_s[2] + red_s[3];

    // ---- Pass 2: coalesced q write (16 warps x 32 rows x 128 cols) ---------
    {
        const int rbase = (wid >> 2) * 32;
        const int cb = (wid & 3) * 128 + lane * 4;
        const int ch = cb >> 6;
        const uint32_t chOff = (uint32_t)ch * 8192;
        const uint32_t inrow = (uint32_t)(lane & 15) * 8;
        float* qb = q_out + (size_t)tile * TM * KC + cb;
        #pragma unroll 4
        for (int r = 0; r < 32; r++) {
            const int row = rbase + r;
            const uint32_t base = (row < 64 ? OFF_BHI + (uint32_t)row * 128
                                            : OFF_BLO + (uint32_t)(row - 64) * 128) + chOff;
            const uint2 u = *reinterpret_cast<const uint2*>(
                smem + base + (inrow ^ (uint32_t)((row & 7) * 16)));
            const float2 f01 = __half22float2(*reinterpret_cast<const __half2*>(&u.x));
            const float2 f23 = __half22float2(*reinterpret_cast<const __half2*>(&u.y));
            const float w = w_s[row * 9 + ch];
            float4 o;
            o.x = f01.x * w; o.y = f01.y * w; o.z = f23.x * w; o.w = f23.y * w;
            *reinterpret_cast<float4*>(qb + (size_t)row * KC) = o;
        }
    }

    // ---- last-CTA loss finalize (deterministic fixed-order sum) ------------
    __threadfence();
    if (tid == 0) {
        const unsigned int old = atomicAdd(&g_done, 1u);
        *flag_s = (old == (unsigned int)(NTILES - 1)) ? 1u : 0u;
    }
    __syncthreads();
    if (*flag_s) {
        double a = 0.0;
        for (int i = tid; i < NTILES; i += 512) a += (double)g_loss_partial[i];
        #pragma unroll
        for (int o = 16; o; o >>= 1) a += __shfl_xor_sync(~0u, a, o);
        double* dred = reinterpret_cast<double*>(smem + OFF_RED + 128);
        if (lane == 0) dred[wid] = a;
        __syncthreads();
        if (tid == 0) {
            double t = 0.0;
            #pragma unroll
            for (int i = 0; i < 16; i++) t += dred[i];
            if (loss_out) *loss_out = (float)(t / (double)B_ROWS);
            g_done = 0;   // reset for next graph replay
        }
    }
}

// ============================================================================
// Launch
// ============================================================================
extern "C" void kernel_launch(void* const* d_in, const int* in_sizes, int n_in,
                              void* d_out, int out_size) {
    const float* z  = (const float*)d_in[0];
    const float* cc = (const float*)d_in[1];
    float* q = (float*)d_out;

    const long long q_elems = (long long)B_ROWS * KC;  // 67108864
    float* loss_out = ((long long)out_size > q_elems) ? (q + q_elems) : nullptr;

    cudaFuncSetAttribute(soft_kmeans_kernel,
                         cudaFuncAttributeMaxDynamicSharedMemorySize, SMEM_BYTES);
    soft_kmeans_kernel<<<NTILES, 512, SMEM_BYTES>>>(z, cc, q, loss_out);
}